// round 4
// baseline (speedup 1.0000x reference)
#include <cuda_runtime.h>

// ---------------------------------------------------------------------------
// QuantumNet: 2-qubit circuit collapsed to a 3x3 bilinear form.
//
//   out = u0^T A u1,   u_i = (1, cos x_i, sin x_i)
//
// Derivation: out = p^T R p with p = (c0c1, c0s1, s0c1, -s0s1),
// ci = cos(x_i/2), si = sin(x_i/2). Half-angle products are linear in the
// full-angle cos/sin:  c^2=(1+C)/2, s^2=(1-C)/2, cs=S/2. R depends only on
// q_weights, so A (9 floats) is a constant of the launch. Each block computes
// A redundantly (thread 0, ~300 cyc) -> single kernel, no prep launch.
// ---------------------------------------------------------------------------

__device__ __forceinline__ float2 cmul(float2 a, float2 b) {
    return make_float2(fmaf(a.x, b.x, -a.y * b.y), fmaf(a.x, b.y, a.y * b.x));
}
__device__ __forceinline__ float2 cadd(float2 a, float2 b) {
    return make_float2(a.x + b.x, a.y + b.y);
}

// e-vector for a half-angle pair product f_a * f_b in basis (1, C, S)
__device__ __forceinline__ void evec(int a, int b, float* e) {
    e[0] = 0.0f; e[1] = 0.0f; e[2] = 0.0f;
    if (a == b) { e[0] = 0.5f; e[1] = (a == 0) ? 0.5f : -0.5f; }
    else        { e[2] = 0.5f; }
}

__device__ void compute_A(const float* __restrict__ w, int n_layers, float* A) {
    // U = I (4x4 complex), basis index = 2*q0 + q1
    float2 U[4][4];
    for (int r = 0; r < 4; r++)
        for (int k = 0; k < 4; k++)
            U[r][k] = make_float2(r == k ? 1.0f : 0.0f, 0.0f);

    for (int l = 0; l < n_layers; l++) {
        float w0 = w[2 * l + 0];
        float w1 = w[2 * l + 1];
        // RX on qubit 0: mixes row pairs (0,2) and (1,3)
        {
            float c = cosf(0.5f * w0), s = sinf(0.5f * w0);
            float2 fc = make_float2(c, 0.0f);
            float2 fs = make_float2(0.0f, -s);   // -i*sin
            for (int k = 0; k < 4; k++)
                for (int base = 0; base < 2; base++) {
                    float2 t0 = U[base][k], t2 = U[base + 2][k];
                    U[base][k]     = cadd(cmul(fc, t0), cmul(fs, t2));
                    U[base + 2][k] = cadd(cmul(fs, t0), cmul(fc, t2));
                }
        }
        // RX on qubit 1: mixes row pairs (0,1) and (2,3)
        {
            float c = cosf(0.5f * w1), s = sinf(0.5f * w1);
            float2 fc = make_float2(c, 0.0f);
            float2 fs = make_float2(0.0f, -s);
            for (int k = 0; k < 4; k++)
                for (int base = 0; base < 4; base += 2) {
                    float2 t0 = U[base][k], t1 = U[base + 1][k];
                    U[base][k]     = cadd(cmul(fc, t0), cmul(fs, t1));
                    U[base + 1][k] = cadd(cmul(fs, t0), cmul(fc, t1));
                }
        }
        // CNOT (control q0, target q1): swap rows 2 and 3
        for (int k = 0; k < 4; k++) {
            float2 t = U[2][k]; U[2][k] = U[3][k]; U[3][k] = t;
        }
    }

    // R'_jk = sgn_j sgn_k * Re( conj(d_j) * M_jk * d_k ),
    //   M_jk = sum_{r in {0,1}} conj(U[r][j]) U[r][k],  d = (1,-i,-i,1)
    const float sgn[4] = {1.0f, 1.0f, 1.0f, -1.0f};
    float2 d[4] = { make_float2(1, 0), make_float2(0, -1),
                    make_float2(0, -1), make_float2(1, 0) };
    float Rm[4][4];
    for (int j = 0; j < 4; j++)
        for (int k = 0; k < 4; k++) {
            float2 m = make_float2(0.0f, 0.0f);
            for (int r = 0; r < 2; r++) {
                float2 cj = make_float2(U[r][j].x, -U[r][j].y);
                m = cadd(m, cmul(cj, U[r][k]));
            }
            float2 cdj = make_float2(d[j].x, -d[j].y);
            float2 v = cmul(cmul(cdj, m), d[k]);
            Rm[j][k] = sgn[j] * sgn[k] * v.x;
        }

    // A[m*3+n] = sum_{jk} R'_jk * e(a0j,a0k)[m] * e(a1j,a1k)[n]
    for (int i = 0; i < 9; i++) A[i] = 0.0f;
    for (int j = 0; j < 4; j++)
        for (int k = 0; k < 4; k++) {
            float e0[3], e1[3];
            evec(j >> 1, k >> 1, e0);
            evec(j & 1,  k & 1,  e1);
            for (int m = 0; m < 3; m++)
                for (int n = 0; n < 3; n++)
                    A[m * 3 + n] = fmaf(Rm[j][k], e0[m] * e1[n], A[m * 3 + n]);
        }
}

__device__ __forceinline__ float eval_sample(float x0, float x1, const float* A) {
    float S0, C0, S1, C1;
    __sincosf(x0, &S0, &C0);
    __sincosf(x1, &S1, &C1);
    // t_n = A[0][n] + A[1][n]*C0 + A[2][n]*S0 ; out = t_0 + t_1*C1 + t_2*S1
    float t0 = fmaf(A[3], C0, fmaf(A[6], S0, A[0]));
    float t1 = fmaf(A[4], C0, fmaf(A[7], S0, A[1]));
    float t2 = fmaf(A[5], C0, fmaf(A[8], S0, A[2]));
    return fmaf(t1, C1, fmaf(t2, S1, t0));
}

__global__ void __launch_bounds__(256)
qnet_kernel(const float* __restrict__ x, float* __restrict__ out, int n,
            const float* __restrict__ w, int n_layers) {
    __shared__ float sA[9];
    if (threadIdx.x == 0) {
        float A[9];
        compute_A(w, n_layers, A);
        for (int i = 0; i < 9; i++) sA[i] = A[i];
    }
    __syncthreads();

    float A[9];
#pragma unroll
    for (int i = 0; i < 9; i++) A[i] = sA[i];

    long long t = (long long)blockIdx.x * blockDim.x + threadIdx.x;
    long long base = t * 8;   // 8 samples per thread

    if (base + 7 < (long long)n) {
        // 4 front-batched float4 loads (MLP=4), 2 float4 stores
        const float4* x4 = (const float4*)x;
        float4 a = x4[t * 4 + 0];
        float4 b = x4[t * 4 + 1];
        float4 c = x4[t * 4 + 2];
        float4 d = x4[t * 4 + 3];
        float4 o0, o1;
        o0.x = eval_sample(a.x, a.y, A);
        o0.y = eval_sample(a.z, a.w, A);
        o0.z = eval_sample(b.x, b.y, A);
        o0.w = eval_sample(b.z, b.w, A);
        o1.x = eval_sample(c.x, c.y, A);
        o1.y = eval_sample(c.z, c.w, A);
        o1.z = eval_sample(d.x, d.y, A);
        o1.w = eval_sample(d.z, d.w, A);
        float4* out4 = (float4*)out;
        out4[t * 2 + 0] = o0;
        out4[t * 2 + 1] = o1;
    } else {
        for (long long i = base; i < (long long)n; i++)
            out[i] = eval_sample(x[2 * i + 0], x[2 * i + 1], A);
    }
}

extern "C" void kernel_launch(void* const* d_in, const int* in_sizes, int n_in,
                              void* d_out, int out_size) {
    const float* x = (const float*)d_in[0];        // [B, 2] float32
    const float* w = (const float*)d_in[1];        // [N_LAYERS, 2] float32
    float* out = (float*)d_out;                    // [B, 1] float32

    int n = in_sizes[0] / 2;          // samples B
    int n_layers = in_sizes[1] / 2;

    long long threads = ((long long)n + 7) / 8;
    int blocks = (int)((threads + 255) / 256);
    qnet_kernel<<<blocks, 256>>>(x, out, n, w, n_layers);
}

// round 6
// speedup vs baseline: 1.0151x; 1.0151x over previous
#include <cuda_runtime.h>

// ---------------------------------------------------------------------------
// QuantumNet: 2-qubit circuit collapsed to a 3x3 bilinear form.
//
//   out = u0^T A u1,   u_i = (1, cos x_i, sin x_i)
//
// p = (c0c1, c0s1, s0c1, -s0s1), ci = cos(x_i/2): out = p^T R p. Half-angle
// products are linear in full-angle cos/sin (c^2=(1+C)/2, s^2=(1-C)/2,
// cs=S/2), so the quartic form collapses to 3x3 bilinear. A depends only on
// q_weights -> 1-thread prep kernel; streaming kernel stays lean (reg-capped).
// ---------------------------------------------------------------------------

__device__ float d_A[9];

__device__ __forceinline__ float2 cmul(float2 a, float2 b) {
    return make_float2(fmaf(a.x, b.x, -a.y * b.y), fmaf(a.x, b.y, a.y * b.x));
}
__device__ __forceinline__ float2 cadd(float2 a, float2 b) {
    return make_float2(a.x + b.x, a.y + b.y);
}

// basis coefficients of the half-angle product f_a*f_b in (1, C, S)
__device__ __forceinline__ void evec(int a, int b, float* e) {
    e[0] = 0.0f; e[1] = 0.0f; e[2] = 0.0f;
    if (a == b) { e[0] = 0.5f; e[1] = (a == 0) ? 0.5f : -0.5f; }
    else        { e[2] = 0.5f; }
}

__global__ void prep_kernel(const float* __restrict__ w, int n_layers) {
    if (threadIdx.x != 0 || blockIdx.x != 0) return;

    // U = I (4x4 complex), basis index = 2*q0 + q1
    float2 U[4][4];
    for (int r = 0; r < 4; r++)
        for (int k = 0; k < 4; k++)
            U[r][k] = make_float2(r == k ? 1.0f : 0.0f, 0.0f);

    for (int l = 0; l < n_layers; l++) {
        float w0 = w[2 * l + 0];
        float w1 = w[2 * l + 1];
        {   // RX on qubit 0: mixes row pairs (0,2) and (1,3)
            float c = cosf(0.5f * w0), s = sinf(0.5f * w0);
            float2 fc = make_float2(c, 0.0f);
            float2 fs = make_float2(0.0f, -s);   // -i*sin
            for (int k = 0; k < 4; k++)
                for (int base = 0; base < 2; base++) {
                    float2 t0 = U[base][k], t2 = U[base + 2][k];
                    U[base][k]     = cadd(cmul(fc, t0), cmul(fs, t2));
                    U[base + 2][k] = cadd(cmul(fs, t0), cmul(fc, t2));
                }
        }
        {   // RX on qubit 1: mixes row pairs (0,1) and (2,3)
            float c = cosf(0.5f * w1), s = sinf(0.5f * w1);
            float2 fc = make_float2(c, 0.0f);
            float2 fs = make_float2(0.0f, -s);
            for (int k = 0; k < 4; k++)
                for (int base = 0; base < 4; base += 2) {
                    float2 t0 = U[base][k], t1 = U[base + 1][k];
                    U[base][k]     = cadd(cmul(fc, t0), cmul(fs, t1));
                    U[base + 1][k] = cadd(cmul(fs, t0), cmul(fc, t1));
                }
        }
        // CNOT (control q0, target q1): swap rows 2 and 3
        for (int k = 0; k < 4; k++) {
            float2 t = U[2][k]; U[2][k] = U[3][k]; U[3][k] = t;
        }
    }

    // R'_jk = sgn_j sgn_k * Re( conj(d_j) * M_jk * d_k ),
    //   M_jk = sum_{r in {0,1}} conj(U[r][j]) U[r][k],  d = (1,-i,-i,1)
    const float sgn[4] = {1.0f, 1.0f, 1.0f, -1.0f};
    float2 d[4] = { make_float2(1, 0), make_float2(0, -1),
                    make_float2(0, -1), make_float2(1, 0) };
    float Rm[4][4];
    for (int j = 0; j < 4; j++)
        for (int k = 0; k < 4; k++) {
            float2 m = make_float2(0.0f, 0.0f);
            for (int r = 0; r < 2; r++) {
                float2 cj = make_float2(U[r][j].x, -U[r][j].y);
                m = cadd(m, cmul(cj, U[r][k]));
            }
            float2 cdj = make_float2(d[j].x, -d[j].y);
            float2 v = cmul(cmul(cdj, m), d[k]);
            Rm[j][k] = sgn[j] * sgn[k] * v.x;
        }

    // A[m*3+n] = sum_{jk} R'_jk * e(q0_j,q0_k)[m] * e(q1_j,q1_k)[n]
    float A[9];
    for (int i = 0; i < 9; i++) A[i] = 0.0f;
    for (int j = 0; j < 4; j++)
        for (int k = 0; k < 4; k++) {
            float e0[3], e1[3];
            evec(j >> 1, k >> 1, e0);
            evec(j & 1,  k & 1,  e1);
            for (int m = 0; m < 3; m++)
                for (int nn = 0; nn < 3; nn++)
                    A[m * 3 + nn] = fmaf(Rm[j][k], e0[m] * e1[nn], A[m * 3 + nn]);
        }
    for (int i = 0; i < 9; i++) d_A[i] = A[i];
}

__device__ __forceinline__ float eval_sample(float x0, float x1, const float* A) {
    float S0, C0, S1, C1;
    __sincosf(x0, &S0, &C0);
    __sincosf(x1, &S1, &C1);
    float t0 = fmaf(A[3], C0, fmaf(A[6], S0, A[0]));
    float t1 = fmaf(A[4], C0, fmaf(A[7], S0, A[1]));
    float t2 = fmaf(A[5], C0, fmaf(A[8], S0, A[2]));
    return fmaf(t1, C1, fmaf(t2, S1, t0));
}

__global__ void __launch_bounds__(256, 6)
qnet_kernel(const float* __restrict__ x, float* __restrict__ out, int n) {
    float A[9];
    {
        const float* __restrict__ pA = d_A;
#pragma unroll
        for (int i = 0; i < 9; i++) A[i] = __ldg(pA + i);  // uniform broadcast
    }

    long long t = (long long)blockIdx.x * blockDim.x + threadIdx.x;
    long long base = t * 8;   // 8 samples per thread

    if (base + 7 < (long long)n) {
        // 4 front-batched LDG.128 (MLP=4), 2 STG.128
        const float4* x4 = (const float4*)x;
        float4 a = x4[t * 4 + 0];
        float4 b = x4[t * 4 + 1];
        float4 c = x4[t * 4 + 2];
        float4 d = x4[t * 4 + 3];
        float4 o0, o1;
        o0.x = eval_sample(a.x, a.y, A);
        o0.y = eval_sample(a.z, a.w, A);
        o0.z = eval_sample(b.x, b.y, A);
        o0.w = eval_sample(b.z, b.w, A);
        o1.x = eval_sample(c.x, c.y, A);
        o1.y = eval_sample(c.z, c.w, A);
        o1.z = eval_sample(d.x, d.y, A);
        o1.w = eval_sample(d.z, d.w, A);
        float4* out4 = (float4*)out;
        out4[t * 2 + 0] = o0;
        out4[t * 2 + 1] = o1;
    } else {
        for (long long i = base; i < (long long)n; i++)
            out[i] = eval_sample(x[2 * i + 0], x[2 * i + 1], A);
    }
}

extern "C" void kernel_launch(void* const* d_in, const int* in_sizes, int n_in,
                              void* d_out, int out_size) {
    const float* x = (const float*)d_in[0];        // [B, 2] float32
    const float* w = (const float*)d_in[1];        // [N_LAYERS, 2] float32
    float* out = (float*)d_out;                    // [B, 1] float32

    int n = in_sizes[0] / 2;          // samples B
    int n_layers = in_sizes[1] / 2;

    prep_kernel<<<1, 1>>>(w, n_layers);

    long long threads = ((long long)n + 7) / 8;
    int blocks = (int)((threads + 255) / 256);
    qnet_kernel<<<blocks, 256>>>(x, out, n);
}